// round 1
// baseline (speedup 1.0000x reference)
#include <cuda_runtime.h>
#include <cstdint>

// QuantizationLayer: out[i*4 + {0..3}] = bits (MSB-first) of round_half_even(x[i]*16 - 0.5)
// x: (32768, 512) f32 in [0,1)  ->  out: (32768, 2048) f32 of {0.0, 1.0}
//
// Pure streaming kernel: 1 thread per input element.
//   - coalesced 4B load per thread
//   - coalesced 16B (float4) store per thread (4 output floats are contiguous)
__global__ void quant_unpack_kernel(const float* __restrict__ x,
                                    float4* __restrict__ out,
                                    int n) {
    int i = blockIdx.x * blockDim.x + threadIdx.x;
    if (i >= n) return;

    float v = x[i];
    // round-half-to-even (rintf honors RN mode = nearest-even), matches jnp.round
    int c = (int)rintf(fmaf(v, 16.0f, -0.5f));
    // clamp defensively (mathematically c in [0,15] since 0 <= v < 1)
    c &= 15;

    float4 bits;
    bits.x = (float)((c >> 3) & 1);
    bits.y = (float)((c >> 2) & 1);
    bits.z = (float)((c >> 1) & 1);
    bits.w = (float)(c & 1);

    out[i] = bits;  // writes out_float[4*i .. 4*i+3]
}

extern "C" void kernel_launch(void* const* d_in, const int* in_sizes, int n_in,
                              void* d_out, int out_size) {
    const float* x = (const float*)d_in[0];
    // d_in[1] is B (=4), compile-time assumed per reference shapes
    float4* out = (float4*)d_out;
    int n = in_sizes[0];  // 32768*512 = 16,777,216

    const int threads = 256;
    int blocks = (n + threads - 1) / threads;
    quant_unpack_kernel<<<blocks, threads>>>(x, out, n);
}

// round 2
// speedup vs baseline: 1.1885x; 1.1885x over previous
#include <cuda_runtime.h>
#include <cstdint>

// QuantizationLayer: out[i*4 + {0..3}] = bits (MSB-first) of round_half_even(x[i]*16 - 0.5)
// x: (32768, 512) f32 in [0,1)  ->  out: (32768, 2048) f32 of {0.0, 1.0}
//
// Streaming kernel, 4 elements per thread (strided by blockDim so each
// LDG is a coalesced 128B/warp and each STG.128 is a coalesced 512B/warp).
// __ldcs/__stcs: evict-first streaming hints — output is write-once,
// input is read-once; don't let them churn L2.

#define ELEMS_PER_THREAD 4

__global__ void quant_unpack_kernel(const float* __restrict__ x,
                                    float4* __restrict__ out,
                                    int n) {
    int base = blockIdx.x * (blockDim.x * ELEMS_PER_THREAD) + threadIdx.x;

    float v[ELEMS_PER_THREAD];
    int idx[ELEMS_PER_THREAD];

    // Phase 1: issue all loads (independent -> MLP=4 per thread)
#pragma unroll
    for (int k = 0; k < ELEMS_PER_THREAD; k++) {
        idx[k] = base + k * blockDim.x;
        v[k] = (idx[k] < n) ? __ldcs(x + idx[k]) : 0.0f;
    }

    // Phase 2: compute + store
#pragma unroll
    for (int k = 0; k < ELEMS_PER_THREAD; k++) {
        if (idx[k] >= n) continue;
        // round-half-to-even (rintf = RN nearest-even), matches jnp.round.
        // x*16 exact (pow2 scale), -0.5 exact, code in [0,15].
        int c = (int)rintf(fmaf(v[k], 16.0f, -0.5f));
        c &= 15;

        float4 bits;
        bits.x = (float)((c >> 3) & 1);
        bits.y = (float)((c >> 2) & 1);
        bits.z = (float)((c >> 1) & 1);
        bits.w = (float)(c & 1);

        __stcs(out + idx[k], bits);  // writes out_float[4*idx .. 4*idx+3]
    }
}

extern "C" void kernel_launch(void* const* d_in, const int* in_sizes, int n_in,
                              void* d_out, int out_size) {
    const float* x = (const float*)d_in[0];
    float4* out = (float4*)d_out;
    int n = in_sizes[0];  // 32768*512 = 16,777,216

    const int threads = 256;
    const int per_block = threads * ELEMS_PER_THREAD;
    int blocks = (n + per_block - 1) / per_block;
    quant_unpack_kernel<<<blocks, threads>>>(x, out, n);
}